// round 10
// baseline (speedup 1.0000x reference)
#include <cuda_runtime.h>
#include <cuda_fp16.h>

#define I_DIM   128
#define O_DIM   128
#define G_NUM   128
#define G1      129
#define B_DIM   8192
#define C_CHUNKS 4
#define ICHUNK  (I_DIM / C_CHUNKS)   /* 32 */
#define BT      256                  /* batch columns per block */
#define NBT     (B_DIM / BT)         /* 32 */
#define THREADS 512
#define NWARP   (THREADS / 32)       /* 16 */
#define BPW     (BT / NWARP)         /* 16 batch columns per warp */
#define ROW_U2  (O_DIM / 4)          /* 32 uint2 per 256B fp16 row */
#define TI      16                   /* i per transpose tile */

// Static device scratch (allocation-free per harness rules)
__device__ __align__(256) __half g_P2h[(size_t)I_DIM * G1 * O_DIM];   // [i][g][o] 4.2MB
__device__ __align__(16) __half g_partialH[C_CHUNKS][B_DIM][O_DIM];   // [c][b][o] fp16 8MB

// ---------------------------------------------------------------------------
// Kernel 1: transpose+quantize P[g][o][i] -> P2h[i][g][o].
// Tile = 2 g's x 16 i's, 256 threads, smem 17.4KB -> grid 520 blocks,
// 4-5 blocks/SM resident: enough warps to cover cold-DRAM latency.
// ---------------------------------------------------------------------------
__global__ __launch_bounds__(256, 8)
void transpose_kernel(const float* __restrict__ P) {
    __shared__ float tile[2][O_DIM][17];
    const int g0 = blockIdx.y * 2;       // 0,2,...,128
    const int i0 = blockIdx.x * TI;      // 0..112
    const int t = threadIdx.x;
    const int w = t >> 5, lane = t & 31;
    const int gg = w >> 2;               // 0..1: which g this warp serves
    const int w2 = w & 3;                // 0..3: warp within the g
    const int oq = lane >> 2;            // 0..7
    const int f4 = lane & 3;             // 0..3 (float4 within 16-i row)
    const int g = g0 + gg;

    if (g <= G_NUM) {
        const float4* src = (const float4*)(P + (size_t)g * O_DIM * I_DIM + i0);
        float4 v[4];
#pragma unroll
        for (int r = 0; r < 4; r++) {
            int o = w2 * 32 + r * 8 + oq;
            v[r] = src[(size_t)o * (I_DIM / 4) + f4];
        }
#pragma unroll
        for (int r = 0; r < 4; r++) {
            int o = w2 * 32 + r * 8 + oq;
            tile[gg][o][f4 * 4 + 0] = v[r].x;
            tile[gg][o][f4 * 4 + 1] = v[r].y;
            tile[gg][o][f4 * 4 + 2] = v[r].z;
            tile[gg][o][f4 * 4 + 3] = v[r].w;
        }
    }
    __syncthreads();

    const int op  = t & 63;          // o-pair index 0..63
    const int il  = (t >> 6) & 1;    // 0..1
    const int gg2 = t >> 7;          // 0..1
    const int gs  = g0 + gg2;
    if (gs <= G_NUM) {
        __half2* dst = (__half2*)g_P2h;
#pragma unroll
        for (int r = 0; r < 8; r++) {
            int i = il + 2 * r;          // 0..15 (in tile bounds)
            dst[((size_t)(i0 + i) * G1 + gs) * (O_DIM / 2) + op] =
                __floats2half2_rn(tile[gg2][2 * op][i], tile[gg2][2 * op + 1][i]);
        }
    }
}

// ---------------------------------------------------------------------------
// Kernel 2 (round-4 gather, PROVEN fastest): Block = 256 b x 32 i.
// Warp handles 16 batch cols; lane covers 4 outputs (uint2).
// NEW: partials stored as packed half2 (uint2) -> halves store traffic.
// ---------------------------------------------------------------------------
__global__ __launch_bounds__(THREADS, 1)
void main_kernel(const float* __restrict__ x,
                 const float* __restrict__ borders,
                 const float* __restrict__ invl) {
    __shared__ __align__(16) unsigned s_gd[ICHUNK][BT];   // 32 KB
    __shared__ float s_b[G1];
    __shared__ float s_il[G_NUM];

    const int t     = threadIdx.x;
    const int btile = blockIdx.x;    // 0..31
    const int chunk = blockIdx.y;    // 0..3
    const int b0    = btile * BT;
    const int i0    = chunk * ICHUNK;

    if (t < G1)    s_b[t]  = borders[t];
    if (t < G_NUM) s_il[t] = invl[t];
    __syncthreads();

    // Phase 1: bucket index g + weight d, packed (g | half(d)<<16)
    {
        const int bl    = t & (BT - 1);
        const int ibase = t >> 8;
#pragma unroll
        for (int p = 0; p < ICHUNK / 2; p++) {
            int il = ibase + 2 * p;
            float xv = x[(size_t)(i0 + il) * B_DIM + b0 + bl];
            float e  = __expf(-fabsf(xv));
            float cdf = (xv > 0.f) ? (1.f - 0.5f * e) : (0.5f * e);
            int g = (int)(cdf * (float)G_NUM);
            g = min(max(g, 0), G_NUM - 1);
            float d = (xv - s_b[g]) * s_il[g];
            unsigned db = (unsigned)__half_as_ushort(__float2half_rn(d));
            s_gd[il][bl] = (unsigned)g | (db << 16);
        }
    }
    __syncthreads();

    const int w    = t >> 5;
    const int lane = t & 31;
    const int wb   = w * BPW;

    const __half2 one2 = __floats2half2_rn(1.f, 1.f);
    const __half2 z2   = __floats2half2_rn(0.f, 0.f);
    const uint2* __restrict__ P2v = (const uint2*)g_P2h;

    float4 accF[BPW];
#pragma unroll
    for (int j = 0; j < BPW; j++) accF[j] = make_float4(0.f, 0.f, 0.f, 0.f);

    for (int iiB = 0; iiB < ICHUNK; iiB += 4) {
        __half2 a0[BPW], a1[BPW];
#pragma unroll
        for (int j = 0; j < BPW; j++) { a0[j] = z2; a1[j] = z2; }

#pragma unroll
        for (int u = 0; u < 4; u++) {
            const int ii = iiB + u;
            const uint2* slice = P2v + (size_t)(i0 + ii) * (G1 * ROW_U2);
#pragma unroll
            for (int j = 0; j < BPW; j++) {
                unsigned v  = s_gd[ii][wb + j];     // broadcast LDS
                unsigned gi = v & 0xFFu;
                unsigned dd = __byte_perm(v, v, 0x3232);
                __half2 d2  = *(__half2*)&dd;
                __half2 w2  = __hsub2(one2, d2);
                const uint2* rowp = slice + gi * ROW_U2 + lane;
                uint2 A  = __ldg(rowp);             // row g   (256B coalesced)
                uint2 Bv = __ldg(rowp + ROW_U2);    // row g+1 (adjacent)
                a0[j] = __hfma2(w2, *(__half2*)&A.x,  a0[j]);
                a0[j] = __hfma2(d2, *(__half2*)&Bv.x, a0[j]);
                a1[j] = __hfma2(w2, *(__half2*)&A.y,  a1[j]);
                a1[j] = __hfma2(d2, *(__half2*)&Bv.y, a1[j]);
            }
        }

        // flush half2 partials into fp32 accumulators every 4 slices
#pragma unroll
        for (int j = 0; j < BPW; j++) {
            float2 p0 = __half22float2(a0[j]);
            float2 p1 = __half22float2(a1[j]);
            accF[j].x += p0.x; accF[j].y += p0.y;
            accF[j].z += p1.x; accF[j].w += p1.y;
        }
        // Thinned barrier: re-converge warps every 8 slices only.
        if (iiB & 4) __syncthreads();
    }

    // Coalesced uint2 (packed half2) stores into [c][b][o] scratch.
#pragma unroll
    for (int j = 0; j < BPW; j++) {
        __half2 ph0 = __floats2half2_rn(accF[j].x, accF[j].y);
        __half2 ph1 = __floats2half2_rn(accF[j].z, accF[j].w);
        uint2 pk;
        pk.x = *(unsigned*)&ph0;
        pk.y = *(unsigned*)&ph1;
        ((uint2*)&g_partialH[chunk][b0 + wb + j][0])[lane] = pk;
    }
}

// ---------------------------------------------------------------------------
// Kernel 3: sum the 4 fp16 partials (fp32 math) and transpose -> out[o][b].
// ---------------------------------------------------------------------------
__global__ void reduce_kernel(float* __restrict__ out) {
    __shared__ float4 tile[32][33];
    const int b0 = blockIdx.x * 32;
    const int tx = threadIdx.x, ty = threadIdx.y;   // (32, 8)
    const size_t cstride = (size_t)B_DIM * (O_DIM / 4);   // in uint2

    const uint2* pbase = (const uint2*)&g_partialH[0][0][0];
#pragma unroll
    for (int r = 0; r < 4; r++) {
        int b = ty + r * 8;
        const uint2* p = pbase + (size_t)(b0 + b) * (O_DIM / 4) + tx;
        float4 s = make_float4(0.f, 0.f, 0.f, 0.f);
#pragma unroll
        for (int c = 0; c < C_CHUNKS; c++) {
            uint2 v = p[c * cstride];
            float2 f0 = __half22float2(*(const __half2*)&v.x);
            float2 f1 = __half22float2(*(const __half2*)&v.y);
            s.x += f0.x; s.y += f0.y; s.z += f1.x; s.w += f1.y;
        }
        tile[b][tx] = s;
    }
    __syncthreads();

    const float* tf = (const float*)tile;   // row stride = 132 floats
#pragma unroll
    for (int r = 0; r < 16; r++) {
        int o = ty + r * 8;
        out[(size_t)o * B_DIM + b0 + tx] = tf[tx * 132 + o];
    }
}

// ---------------------------------------------------------------------------
extern "C" void kernel_launch(void* const* d_in, const int* in_sizes, int n_in,
                              void* d_out, int out_size) {
    const float* x       = (const float*)d_in[0];   // [128, 8192]
    const float* P       = (const float*)d_in[1];   // [129, 128, 128]
    const float* borders = (const float*)d_in[2];   // [129]
    const float* invl    = (const float*)d_in[3];   // [128]
    float*       out     = (float*)d_out;           // [128, 8192]

    transpose_kernel<<<dim3(I_DIM / TI, 65), 256>>>(P);
    main_kernel<<<dim3(NBT, C_CHUNKS), THREADS>>>(x, borders, invl);
    reduce_kernel<<<B_DIM / 32, dim3(32, 8)>>>(out);
}